// round 16
// baseline (speedup 1.0000x reference)
#include <cuda_runtime.h>

#define BB 64
#define EE 8978
#define E2C 4489
#define N1 (BB*EE)            // 574592
#define N2 (BB*E2C)           // 287296
#define SLOPE 0.33f
#define EPSBN 1e-5f

// ---------------- device scratch ----------------
__device__ float g_out32[9193472];   // pooled pre-BN (N2*32); later layer1 pre-BN out
__device__ float g_xp  [9193472];    // act0 output = layer1 T0
__device__ float g_Ta  [9193472];    // layer1 T1
__device__ float g_Tb  [9193472];    // layer1 T2
__device__ float g_Tcc [9193472];    // layer1 T3
__device__ float g_Y [N2*4];         // layer2 projected field
__device__ float g_U1[N2*4];
__device__ float g_U2[N2*4];
__device__ float g_z[N2];
__device__ float g_H1[64*256];
__device__ float g_H2[64*128];
__device__ double g_acc0[64];
__device__ double g_acc1[64];
__device__ double g_acc2[2];

// ---------------- init ----------------
__global__ void kZero() {
    int t = threadIdx.x;
    if (t < 64) g_acc0[t] = 0.0;
    else if (t < 128) g_acc1[t - 64] = 0.0;
    else if (t < 130) g_acc2[t - 128] = 0.0;
}

// ---------------- fused layer0: block per graph, fields in smem ----------------
__global__ void kL0(const float* __restrict__ x, const int* __restrict__ src,
                    const float* __restrict__ ew, const float* __restrict__ W0,
                    const float* __restrict__ b0) {
    extern __shared__ float sm[];
    float* xs  = sm;
    float* t1s = sm + EE;
    float* t2s = sm + 2 * EE;
    __shared__ float s_sum[32], s_sq[32];

    int g = blockIdx.x;
    int tid = threadIdx.x;
    int lane = tid & 31, warp = tid >> 5;      // 32 warps of 1024 threads
    int nbase = g * EE;
    int ebase = nbase * 16;

    for (int i = tid; i < EE; i += 1024) xs[i] = x[nbase + i];
    if (tid < 32) { s_sum[tid] = 0.f; s_sq[tid] = 0.f; }
    __syncthreads();

    // step1: T1 = x - L x
    for (int p = warp; p < E2C; p += 32) {
        int e = ebase + p * 32 + lane;
        int ls = src[e] - nbase;
        float a = ew[e] * xs[ls];
        a += __shfl_xor_sync(~0u, a, 8);
        a += __shfl_xor_sync(~0u, a, 4);
        a += __shfl_xor_sync(~0u, a, 2);
        a += __shfl_xor_sync(~0u, a, 1);
        if (lane == 0)  t1s[2 * p]     = xs[2 * p]     - a;
        if (lane == 16) t1s[2 * p + 1] = xs[2 * p + 1] - a;
    }
    __syncthreads();

    // step2: T2 = (3 T1 - L T1 - x) / 2
    for (int p = warp; p < E2C; p += 32) {
        int e = ebase + p * 32 + lane;
        int ls = src[e] - nbase;
        float a = ew[e] * t1s[ls];
        a += __shfl_xor_sync(~0u, a, 8);
        a += __shfl_xor_sync(~0u, a, 4);
        a += __shfl_xor_sync(~0u, a, 2);
        a += __shfl_xor_sync(~0u, a, 1);
        if (lane == 0)  t2s[2 * p]     = 0.5f * (3.f * t1s[2 * p]     - a - xs[2 * p]);
        if (lane == 16) t2s[2 * p + 1] = 0.5f * (3.f * t1s[2 * p + 1] - a - xs[2 * p + 1]);
    }
    __syncthreads();

    // step3: T3 = (5 T2 - L T2 - 2 T1)/3 ; project to 32 ch; pre-BN max pool
    float w0 = W0[lane], w1 = W0[32 + lane], w2 = W0[64 + lane], w3 = W0[96 + lane];
    float bb = b0[lane];
    float lsum = 0.f, lsq = 0.f;
    for (int p = warp; p < E2C; p += 32) {
        int e = ebase + p * 32 + lane;
        int ls = src[e] - nbase;
        float a = ew[e] * t2s[ls];
        a += __shfl_xor_sync(~0u, a, 8);
        a += __shfl_xor_sync(~0u, a, 4);
        a += __shfl_xor_sync(~0u, a, 2);
        a += __shfl_xor_sync(~0u, a, 1);
        float t3 = 0.f;
        if ((lane & 15) == 0) {
            int n = 2 * p + (lane >> 4);
            t3 = (5.f * t2s[n] - a - 2.f * t1s[n]) * (1.f / 3.f);
        }
        float t3a = __shfl_sync(~0u, t3, 0);
        float t3b = __shfl_sync(~0u, t3, 16);
        float xa  = xs[2 * p],  xb  = xs[2 * p + 1];
        float ta1 = t1s[2 * p], tb1 = t1s[2 * p + 1];
        float ta2 = t2s[2 * p], tb2 = t2s[2 * p + 1];
        float oa = fmaf(xa, w0, fmaf(ta1, w1, fmaf(ta2, w2, fmaf(t3a, w3, bb))));
        float ob = fmaf(xb, w0, fmaf(tb1, w1, fmaf(tb2, w2, fmaf(t3b, w3, bb))));
        lsum += oa + ob;
        lsq  += oa * oa + ob * ob;
        g_out32[((size_t)(g * E2C + p)) * 32 + lane] = fmaxf(oa, ob);
    }
    atomicAdd(&s_sum[lane], lsum);
    atomicAdd(&s_sq[lane], lsq);
    __syncthreads();
    if (tid < 32) {
        atomicAdd(&g_acc0[tid],      (double)s_sum[tid]);
        atomicAdd(&g_acc0[32 + tid], (double)s_sq[tid]);
    }
}

// ---------------- act0: BN0 finalize (in-block) + BN0 + LeakyReLU (float4) ----
__global__ void kAct0v(const float* __restrict__ g0, const float* __restrict__ be0) {
    __shared__ float s_sc[32], s_sh[32];
    int tid = threadIdx.x;
    if (tid < 32) {
        double mean = g_acc0[tid] / (double)N1;
        double var  = g_acc0[32 + tid] / (double)N1 - mean * mean;
        float scl = g0[tid] * rsqrtf((float)var + EPSBN);
        s_sc[tid] = scl;
        s_sh[tid] = be0[tid] - (float)mean * scl;
    }
    __syncthreads();
    int i = blockIdx.x * 256 + tid;                // over N2*8 float4s
    int cq = i & 7;
    float4 v = *(const float4*)&g_out32[i * 4];
    float4 sc = *(const float4*)&s_sc[cq * 4];
    float4 sh = *(const float4*)&s_sh[cq * 4];
    v.x = fmaf(v.x, sc.x, sh.x); v.x = v.x > 0.f ? v.x : SLOPE * v.x;
    v.y = fmaf(v.y, sc.y, sh.y); v.y = v.y > 0.f ? v.y : SLOPE * v.y;
    v.z = fmaf(v.z, sc.z, sh.z); v.z = v.z > 0.f ? v.z : SLOPE * v.z;
    v.w = fmaf(v.w, sc.w, sh.w); v.w = v.w > 0.f ? v.w : SLOPE * v.w;
    *(float4*)&g_xp[i * 4] = v;
}

// ---------------- pooled-graph 32-ch matvec, float4 + 2-node-group ILP --------
// warp = 8 nodes (two groups of 4). lane = (node_sub, channel-quad).
// Two independent accumulator sets -> 32 outstanding gathers per warp.
__global__ void kMV4(const float* __restrict__ vin, const float* __restrict__ p1,
                     const int* __restrict__ src, const float* __restrict__ ew,
                     float* __restrict__ out, float ca, float cb, float cc) {
    int warp = (blockIdx.x * blockDim.x + threadIdx.x) >> 5;   // 8-node group
    int lane = threadIdx.x & 31;
    int ns = lane >> 3, cq = lane & 7;
    int nodeA = warp * 8 + ns;
    int nodeB = nodeA + 4;
    int eA = nodeA * 16 + cq;
    int eB = nodeB * 16 + cq;
    int   sA0 = src[eA];     float wA0 = ew[eA];
    int   sA1 = src[eA + 8]; float wA1 = ew[eA + 8];
    int   sB0 = src[eB];     float wB0 = ew[eB];
    int   sB1 = src[eB + 8]; float wB1 = ew[eB + 8];
    int sl = ns * 8;
    float4 accA = make_float4(0.f, 0.f, 0.f, 0.f);
    float4 accB = make_float4(0.f, 0.f, 0.f, 0.f);
#pragma unroll
    for (int j = 0; j < 8; j++) {
        int   saj = __shfl_sync(~0u, sA0, sl + j);
        float waj = __shfl_sync(~0u, wA0, sl + j);
        int   sbj = __shfl_sync(~0u, sB0, sl + j);
        float wbj = __shfl_sync(~0u, wB0, sl + j);
        float4 va = *(const float4*)&vin[saj * 32 + cq * 4];
        float4 vb = *(const float4*)&vin[sbj * 32 + cq * 4];
        accA.x = fmaf(waj, va.x, accA.x); accA.y = fmaf(waj, va.y, accA.y);
        accA.z = fmaf(waj, va.z, accA.z); accA.w = fmaf(waj, va.w, accA.w);
        accB.x = fmaf(wbj, vb.x, accB.x); accB.y = fmaf(wbj, vb.y, accB.y);
        accB.z = fmaf(wbj, vb.z, accB.z); accB.w = fmaf(wbj, vb.w, accB.w);
    }
#pragma unroll
    for (int j = 0; j < 8; j++) {
        int   saj = __shfl_sync(~0u, sA1, sl + j);
        float waj = __shfl_sync(~0u, wA1, sl + j);
        int   sbj = __shfl_sync(~0u, sB1, sl + j);
        float wbj = __shfl_sync(~0u, wB1, sl + j);
        float4 va = *(const float4*)&vin[saj * 32 + cq * 4];
        float4 vb = *(const float4*)&vin[sbj * 32 + cq * 4];
        accA.x = fmaf(waj, va.x, accA.x); accA.y = fmaf(waj, va.y, accA.y);
        accA.z = fmaf(waj, va.z, accA.z); accA.w = fmaf(waj, va.w, accA.w);
        accB.x = fmaf(wbj, vb.x, accB.x); accB.y = fmaf(wbj, vb.y, accB.y);
        accB.z = fmaf(wbj, vb.z, accB.z); accB.w = fmaf(wbj, vb.w, accB.w);
    }
    float4 ownA = *(const float4*)&vin[nodeA * 32 + cq * 4];
    float4 ownB = *(const float4*)&vin[nodeB * 32 + cq * 4];
    float4 oA, oB;
    oA.x = ca * ownA.x + cc * accA.x; oA.y = ca * ownA.y + cc * accA.y;
    oA.z = ca * ownA.z + cc * accA.z; oA.w = ca * ownA.w + cc * accA.w;
    oB.x = ca * ownB.x + cc * accB.x; oB.y = ca * ownB.y + cc * accB.y;
    oB.z = ca * ownB.z + cc * accB.z; oB.w = ca * ownB.w + cc * accB.w;
    if (cb != 0.f) {
        float4 pA = *(const float4*)&p1[nodeA * 32 + cq * 4];
        float4 pB = *(const float4*)&p1[nodeB * 32 + cq * 4];
        oA.x += cb * pA.x; oA.y += cb * pA.y; oA.z += cb * pA.z; oA.w += cb * pA.w;
        oB.x += cb * pB.x; oB.y += cb * pB.y; oB.z += cb * pB.z; oB.w += cb * pB.w;
    }
    *(float4*)&out[nodeA * 32 + cq * 4] = oA;
    *(float4*)&out[nodeB * 32 + cq * 4] = oB;
}

// ---------------- layer1 output GEMM + BN1 stats (single load phase) ----------
__global__ void kGemmOut1(const float* __restrict__ W1, const float* __restrict__ b1) {
    extern __shared__ float dsm[];
    float* Wsh = dsm;              // 4096 floats
    float* Tsh = dsm + 4096;       // 4 * 2048 floats
    __shared__ float ssum[32], ssq[32];
    int tid = threadIdx.x, c = tid & 31, rg = tid >> 5;
    for (int i = tid; i < 4096; i += 256) Wsh[i] = W1[i];
    if (tid < 32) { ssum[tid] = 0.f; ssq[tid] = 0.f; }
    int n0 = blockIdx.x * 64;
    const float* Tarr[4] = { g_xp, g_Ta, g_Tb, g_Tcc };
    int lrow = tid >> 3, lq = tid & 7;
#pragma unroll
    for (int k = 0; k < 4; k++) {
        const float* T = Tarr[k];
#pragma unroll
        for (int h = 0; h < 2; h++) {
            int row = lrow + h * 32;
            *(float4*)&Tsh[k * 2048 + row * 32 + lq * 4] =
                *(const float4*)&T[(size_t)(n0 + row) * 32 + lq * 4];
        }
    }
    __syncthreads();
    float acc[8];
#pragma unroll
    for (int q = 0; q < 8; q++) acc[q] = 0.f;
#pragma unroll
    for (int k = 0; k < 4; k++) {
#pragma unroll
        for (int i = 0; i < 32; i += 4) {
            float wa = Wsh[(k * 32 + i) * 32 + c];
            float wb = Wsh[(k * 32 + i + 1) * 32 + c];
            float wc = Wsh[(k * 32 + i + 2) * 32 + c];
            float wd = Wsh[(k * 32 + i + 3) * 32 + c];
#pragma unroll
            for (int q = 0; q < 8; q++) {
                float4 t = *(const float4*)&Tsh[k * 2048 + (rg + 8 * q) * 32 + i];
                acc[q] += t.x * wa + t.y * wb + t.z * wc + t.w * wd;
            }
        }
    }
    float bv = b1[c];
    float lsum = 0.f, lsq = 0.f;
#pragma unroll
    for (int q = 0; q < 8; q++) {
        float o = acc[q] + bv;
        g_out32[(size_t)(n0 + rg + 8 * q) * 32 + c] = o;
        lsum += o; lsq += o * o;
    }
    atomicAdd(&ssum[c], lsum);
    atomicAdd(&ssq[c], lsq);
    __syncthreads();
    if (tid < 32) {
        atomicAdd(&g_acc1[tid], (double)ssum[tid]);
        atomicAdd(&g_acc1[32 + tid], (double)ssq[tid]);
    }
}

// ---------------- layer2 input: BN1 finalize + act + W2 projection ------------
// block = 64 nodes, smem transpose; thread (node, k) computes y_k[node].
__global__ void kAct1Y2(const float* __restrict__ W2,
                        const float* __restrict__ g1, const float* __restrict__ be1) {
    __shared__ float s_sc[32], s_sh[32], Wsh2[128];
    __shared__ float sm[64 * 36];          // padded stride 36 (16B-aligned rows)
    int tid = threadIdx.x;
    if (tid < 32) {
        double mean = g_acc1[tid] / (double)N2;
        double var  = g_acc1[32 + tid] / (double)N2 - mean * mean;
        float scl = g1[tid] * rsqrtf((float)var + EPSBN);
        s_sc[tid] = scl;
        s_sh[tid] = be1[tid] - (float)mean * scl;
    }
    if (tid < 128) Wsh2[tid] = W2[tid];
    __syncthreads();
    int base = blockIdx.x * 64;
#pragma unroll
    for (int h = 0; h < 2; h++) {
        int t = tid + h * 256;
        int row = t >> 3, q = t & 7;
        float4 v = *(const float4*)&g_out32[(size_t)(base + row) * 32 + q * 4];
        float4 sc = *(const float4*)&s_sc[q * 4];
        float4 sh = *(const float4*)&s_sh[q * 4];
        v.x = fmaf(v.x, sc.x, sh.x); v.x = v.x > 0.f ? v.x : SLOPE * v.x;
        v.y = fmaf(v.y, sc.y, sh.y); v.y = v.y > 0.f ? v.y : SLOPE * v.y;
        v.z = fmaf(v.z, sc.z, sh.z); v.z = v.z > 0.f ? v.z : SLOPE * v.z;
        v.w = fmaf(v.w, sc.w, sh.w); v.w = v.w > 0.f ? v.w : SLOPE * v.w;
        *(float4*)&sm[row * 36 + q * 4] = v;
    }
    __syncthreads();
    int node = tid >> 2, k = tid & 3;
    float acc = 0.f;
#pragma unroll
    for (int c = 0; c < 32; c++)
        acc = fmaf(sm[node * 36 + c], Wsh2[k * 32 + c], acc);
    g_Y[(size_t)(base + node) * 4 + k] = acc;
}

// ---------------- 4-channel matvec on Y-field (layer2 recurrence) -------------
__global__ void kMVY(const float* __restrict__ vin, const float* __restrict__ p1,
                     const int* __restrict__ src, const float* __restrict__ ew,
                     float* __restrict__ out, float ca, float cb, float cc) {
    __shared__ int   s_src[16 * 65];
    __shared__ float s_ew [16 * 65];
    int tid = threadIdx.x;
    int e0 = blockIdx.x * 1024;
#pragma unroll
    for (int t = tid; t < 1024; t += 256) {
        int j = t & 15, local = t >> 4;
        s_src[j * 65 + local] = src[e0 + t];
        s_ew [j * 65 + local] = ew [e0 + t];
    }
    __syncthreads();
    int lane = tid & 31;
    int local = (tid >> 5) * 8 + (lane >> 2);   // node within block
    int ch = lane & 3;
    int node = blockIdx.x * 64 + local;
    float acc = 0.f;
#pragma unroll
    for (int j = 0; j < 16; j++) {
        int s   = s_src[j * 65 + local];
        float w = s_ew [j * 65 + local];
        acc += w * vin[s * 4 + ch];
    }
    float o = ca * vin[node * 4 + ch] + cc * acc;
    if (cb != 0.f) o += cb * p1[node * 4 + ch];
    out[node * 4 + ch] = o;
}

// final layer2 step: u3 = (5 U2 - L U2 - 2 U1)/3 ; z = Y0 + U1_1 + U2_2 + u3_3 + b2
__global__ void kMVY3C(const int* __restrict__ src, const float* __restrict__ ew,
                       const float* __restrict__ b2) {
    __shared__ int   s_src[16 * 65];
    __shared__ float s_ew [16 * 65];
    __shared__ float bs[2];
    int tid = threadIdx.x;
    int e0 = blockIdx.x * 1024;
    if (tid < 2) bs[tid] = 0.f;
#pragma unroll
    for (int t = tid; t < 1024; t += 256) {
        int j = t & 15, local = t >> 4;
        s_src[j * 65 + local] = src[e0 + t];
        s_ew [j * 65 + local] = ew [e0 + t];
    }
    __syncthreads();
    int lane = tid & 31;
    int local = (tid >> 5) * 8 + (lane >> 2);
    int ch = lane & 3;
    int node = blockIdx.x * 64 + local;
    float acc = 0.f;
#pragma unroll
    for (int j = 0; j < 16; j++) {
        int s   = s_src[j * 65 + local];
        float w = s_ew [j * 65 + local];
        acc += w * g_U2[s * 4 + ch];
    }
    float u2v = g_U2[node * 4 + ch];
    float u1v = g_U1[node * 4 + ch];
    float yv  = g_Y [node * 4 + ch];
    float u3  = (5.f * u2v - acc - 2.f * u1v) * (1.f / 3.f);
    int base = lane & ~3;
    float zY  = __shfl_sync(~0u, yv,  base + 0);
    float zU1 = __shfl_sync(~0u, u1v, base + 1);
    float zU2 = __shfl_sync(~0u, u2v, base + 2);
    float zU3 = __shfl_sync(~0u, u3,  base + 3);
    if (ch == 0) {
        float z = zY + zU1 + zU2 + zU3 + b2[0];
        g_z[node] = z;
        atomicAdd(&bs[0], z);
        atomicAdd(&bs[1], z * z);
    }
    __syncthreads();
    if (tid == 0) {
        atomicAdd(&g_acc2[0], (double)bs[0]);
        atomicAdd(&g_acc2[1], (double)bs[1]);
    }
}

// ---------------- MLP head ----------------
// D1 folds BN2 finalize (from g_acc2) + leaky + lin1
__global__ void kD1(const float* __restrict__ lin1W, const float* __restrict__ lin1b,
                    const float* __restrict__ g2, const float* __restrict__ be2) {
    __shared__ float As[16][64];
    __shared__ float Ws[64][8];
    int tid = threadIdx.x;
    int c = tid & 7, r = tid >> 3;
    int c0 = (blockIdx.x & 31) * 8;
    int r0 = (blockIdx.x >> 5) * 16;
    float scale, shift;
    {
        double mean = g_acc2[0] / (double)N2;
        double var  = g_acc2[1] / (double)N2 - mean * mean;
        scale = g2[0] * rsqrtf((float)var + EPSBN);
        shift = be2[0] - (float)mean * scale;
    }
    float acc = 0.f;
    for (int e0 = 0; e0 < E2C; e0 += 64) {
        __syncthreads();
        for (int t = tid; t < 1024; t += 128) {
            int rr = t >> 6, ii = t & 63, e = e0 + ii;
            float v = 0.f;
            if (e < E2C) {
                float z = g_z[(r0 + rr) * E2C + e] * scale + shift;
                v = z > 0.f ? z : SLOPE * z;
            }
            As[rr][ii] = v;
        }
        for (int t = tid; t < 512; t += 128) {
            int ii = t >> 3, cc = t & 7, e = e0 + ii;
            Ws[ii][cc] = (e < E2C) ? lin1W[e * 256 + c0 + cc] : 0.f;
        }
        __syncthreads();
#pragma unroll 8
        for (int i = 0; i < 64; i++) acc += As[r][i] * Ws[i][c];
    }
    g_H1[(r0 + r) * 256 + c0 + c] = acc + lin1b[c0 + c];
}

__global__ void kD2(const float* __restrict__ bn1g, const float* __restrict__ bn1b,
                    const float* __restrict__ lin2W, const float* __restrict__ lin2b) {
    __shared__ float sc[256], sh[256], As[2][256];
    int tid = threadIdx.x;
    {
        int col = tid;
        float s = 0.f, q = 0.f;
        for (int r = 0; r < 64; r++) { float v = g_H1[r * 256 + col]; s += v; q += v * v; }
        float mean = s * (1.f / 64.f);
        float var  = q * (1.f / 64.f) - mean * mean;
        float scl = bn1g[col] * rsqrtf(var + EPSBN);
        sc[col] = scl; sh[col] = bn1b[col] - mean * scl;
    }
    __syncthreads();
    int r0 = blockIdx.x * 2;
    for (int t = tid; t < 512; t += 256) {
        int rr = t >> 8, k = t & 255;
        float v = g_H1[(r0 + rr) * 256 + k] * sc[k] + sh[k];
        As[rr][k] = v > 0.f ? v : 0.f;
    }
    __syncthreads();
    int c = tid & 127, rr = tid >> 7;
    float acc = lin2b[c];
#pragma unroll 8
    for (int k = 0; k < 256; k++) acc += As[rr][k] * lin2W[k * 128 + c];
    g_H2[(r0 + rr) * 128 + c] = acc;
}

__global__ void kD3(const float* __restrict__ bn2g, const float* __restrict__ bn2b,
                    const float* __restrict__ lin3W, const float* __restrict__ lin3b,
                    float* __restrict__ out) {
    __shared__ float sc[128], sh[128];
    int tid = threadIdx.x;
    if (tid < 128) {
        float s = 0.f, q = 0.f;
        for (int r = 0; r < 64; r++) { float v = g_H2[r * 128 + tid]; s += v; q += v * v; }
        float mean = s * (1.f / 64.f);
        float var  = q * (1.f / 64.f) - mean * mean;
        float scl = bn2g[tid] * rsqrtf(var + EPSBN);
        sc[tid] = scl; sh[tid] = bn2b[tid] - mean * scl;
    }
    __syncthreads();
    int lane = tid & 31, w = tid >> 5;
    for (int r = w; r < 64; r += 8) {
        float acc = 0.f;
        for (int kk = lane; kk < 128; kk += 32) {
            float v = g_H2[r * 128 + kk] * sc[kk] + sh[kk];
            v = v > 0.f ? v : 0.f;
            acc += v * lin3W[kk];
        }
#pragma unroll
        for (int off = 16; off; off >>= 1)
            acc += __shfl_xor_sync(0xffffffffu, acc, off);
        if (lane == 0) out[r] = acc + lin3b[0];
    }
}

// ---------------- host launcher ----------------
extern "C" void kernel_launch(void* const* d_in, const int* in_sizes, int n_in,
                              void* d_out, int out_size) {
    const float* x    = (const float*)d_in[0];
    const int*   src1 = (const int*)  d_in[1];
    const float* ew1  = (const float*)d_in[2];
    const int*   src2 = (const int*)  d_in[3];
    const float* ew2  = (const float*)d_in[4];
    const float* W0 = (const float*)d_in[5];
    const float* b0 = (const float*)d_in[6];
    const float* g0 = (const float*)d_in[7];
    const float* be0= (const float*)d_in[8];
    const float* W1 = (const float*)d_in[9];
    const float* b1 = (const float*)d_in[10];
    const float* g1 = (const float*)d_in[11];
    const float* be1= (const float*)d_in[12];
    const float* W2 = (const float*)d_in[13];
    const float* b2 = (const float*)d_in[14];
    const float* g2 = (const float*)d_in[15];
    const float* be2= (const float*)d_in[16];
    const float* lin1W = (const float*)d_in[17];
    const float* lin1b = (const float*)d_in[18];
    const float* bn1g  = (const float*)d_in[19];
    const float* bn1b  = (const float*)d_in[20];
    const float* lin2W = (const float*)d_in[21];
    const float* lin2b = (const float*)d_in[22];
    const float* bn2g  = (const float*)d_in[23];
    const float* bn2b  = (const float*)d_in[24];
    const float* lin3W = (const float*)d_in[25];
    const float* lin3b = (const float*)d_in[26];
    float* out = (float*)d_out;

    float *pXp, *pTa, *pTb, *pTcc, *pY, *pU1, *pU2;
    cudaGetSymbolAddress((void**)&pXp,  g_xp);
    cudaGetSymbolAddress((void**)&pTa,  g_Ta);
    cudaGetSymbolAddress((void**)&pTb,  g_Tb);
    cudaGetSymbolAddress((void**)&pTcc, g_Tcc);
    cudaGetSymbolAddress((void**)&pY,   g_Y);
    cudaGetSymbolAddress((void**)&pU1,  g_U1);
    cudaGetSymbolAddress((void**)&pU2,  g_U2);

    const int kL0smem = 3 * EE * (int)sizeof(float);      // 107,736 B
    const int kGsmem  = (4096 + 4 * 2048) * (int)sizeof(float);  // 49,152 B
    cudaFuncSetAttribute(kL0, cudaFuncAttributeMaxDynamicSharedMemorySize, kL0smem);
    cudaFuncSetAttribute(kGemmOut1, cudaFuncAttributeMaxDynamicSharedMemorySize, kGsmem);

    kZero<<<1, 256>>>();

    // ---- layer0 fused ----
    kL0<<<BB, 1024, kL0smem>>>(x, src1, ew1, W0, b0);
    kAct0v<<<(N2 * 8) / 256, 256>>>(g0, be0);   // BN0 finalize folded in

    // ---- layer1 (32 channels, pooled graph) — float4 x2-ILP gather matvecs ----
    kMV4<<<N2 / 64, 256>>>(pXp, pXp, src2, ew2, pTa, 1.0f, 0.0f, -1.0f);
    kMV4<<<N2 / 64, 256>>>(pTa, pXp, src2, ew2, pTb, 1.5f, -0.5f, -0.5f);
    kMV4<<<N2 / 64, 256>>>(pTb, pTa, src2, ew2, pTcc, 5.f/3.f, -2.f/3.f, -1.f/3.f);
    kGemmOut1<<<N2 / 64, 256, kGsmem>>>(W1, b1);

    // ---- layer2 collapsed to 4-channel recurrence (BN1 folded into kAct1Y2) ----
    kAct1Y2<<<N2 / 64, 256>>>(W2, g1, be1);
    kMVY<<<N2 / 64, 256>>>(pY,  pY, src2, ew2, pU1, 1.0f, 0.0f, -1.0f);
    kMVY<<<N2 / 64, 256>>>(pU1, pY, src2, ew2, pU2, 1.5f, -0.5f, -0.5f);
    kMVY3C<<<N2 / 64, 256>>>(src2, ew2, b2);

    // ---- MLP head (BN2 finalize folded into kD1) ----
    kD1<<<128, 128>>>(lin1W, lin1b, g2, be2);
    kD2<<<32, 256>>>(bn1g, bn1b, lin2W, lin2b);
    kD3<<<1, 256>>>(bn2g, bn2b, lin3W, lin3b, out);
}

// round 17
// speedup vs baseline: 1.3622x; 1.3622x over previous
#include <cuda_runtime.h>

#define BB 64
#define EE 8978
#define E2C 4489
#define N1 (BB*EE)            // 574592
#define N2 (BB*E2C)           // 287296
#define SLOPE 0.33f
#define EPSBN 1e-5f
#define INV_N1 (1.0/574592.0)
#define INV_N2 (1.0/287296.0)

// ---------------- device scratch ----------------
__device__ float g_out32[9193472];   // pooled pre-BN (N2*32); later layer1 pre-BN out
__device__ float g_xp  [9193472];    // act0 output = layer1 T0
__device__ float g_Ta  [9193472];    // layer1 T1
__device__ float g_Tb  [9193472];    // layer1 T2
__device__ float g_Tcc [9193472];    // layer1 T3
__device__ float g_Y [N2*4];         // layer2 projected field
__device__ float g_U1[N2*4];
__device__ float g_U2[N2*4];
__device__ float g_z[N2];
__device__ float g_H1[64*256];
__device__ float g_H2[64*128];
__device__ double g_acc0[64];
__device__ double g_acc1[64];
__device__ double g_acc2[2];

// ---------------- init ----------------
__global__ void kZero() {
    int t = threadIdx.x;
    if (t < 64) g_acc0[t] = 0.0;
    else if (t < 128) g_acc1[t - 64] = 0.0;
    else if (t < 130) g_acc2[t - 128] = 0.0;
}

// ---------------- fused layer0: block per graph, fields in smem ----------------
__global__ void kL0(const float* __restrict__ x, const int* __restrict__ src,
                    const float* __restrict__ ew, const float* __restrict__ W0,
                    const float* __restrict__ b0) {
    extern __shared__ float sm[];
    float* xs  = sm;
    float* t1s = sm + EE;
    float* t2s = sm + 2 * EE;
    __shared__ float s_sum[32], s_sq[32];

    int g = blockIdx.x;
    int tid = threadIdx.x;
    int lane = tid & 31, warp = tid >> 5;      // 32 warps of 1024 threads
    int nbase = g * EE;
    int ebase = nbase * 16;

    for (int i = tid; i < EE; i += 1024) xs[i] = x[nbase + i];
    if (tid < 32) { s_sum[tid] = 0.f; s_sq[tid] = 0.f; }
    __syncthreads();

    // step1: T1 = x - L x
    for (int p = warp; p < E2C; p += 32) {
        int e = ebase + p * 32 + lane;
        int ls = src[e] - nbase;
        float a = ew[e] * xs[ls];
        a += __shfl_xor_sync(~0u, a, 8);
        a += __shfl_xor_sync(~0u, a, 4);
        a += __shfl_xor_sync(~0u, a, 2);
        a += __shfl_xor_sync(~0u, a, 1);
        if (lane == 0)  t1s[2 * p]     = xs[2 * p]     - a;
        if (lane == 16) t1s[2 * p + 1] = xs[2 * p + 1] - a;
    }
    __syncthreads();

    // step2: T2 = (3 T1 - L T1 - x) / 2
    for (int p = warp; p < E2C; p += 32) {
        int e = ebase + p * 32 + lane;
        int ls = src[e] - nbase;
        float a = ew[e] * t1s[ls];
        a += __shfl_xor_sync(~0u, a, 8);
        a += __shfl_xor_sync(~0u, a, 4);
        a += __shfl_xor_sync(~0u, a, 2);
        a += __shfl_xor_sync(~0u, a, 1);
        if (lane == 0)  t2s[2 * p]     = 0.5f * (3.f * t1s[2 * p]     - a - xs[2 * p]);
        if (lane == 16) t2s[2 * p + 1] = 0.5f * (3.f * t1s[2 * p + 1] - a - xs[2 * p + 1]);
    }
    __syncthreads();

    // step3: T3 = (5 T2 - L T2 - 2 T1)/3 ; project to 32 ch; pre-BN max pool
    float w0 = W0[lane], w1 = W0[32 + lane], w2 = W0[64 + lane], w3 = W0[96 + lane];
    float bb = b0[lane];
    float lsum = 0.f, lsq = 0.f;
    for (int p = warp; p < E2C; p += 32) {
        int e = ebase + p * 32 + lane;
        int ls = src[e] - nbase;
        float a = ew[e] * t2s[ls];
        a += __shfl_xor_sync(~0u, a, 8);
        a += __shfl_xor_sync(~0u, a, 4);
        a += __shfl_xor_sync(~0u, a, 2);
        a += __shfl_xor_sync(~0u, a, 1);
        float t3 = 0.f;
        if ((lane & 15) == 0) {
            int n = 2 * p + (lane >> 4);
            t3 = (5.f * t2s[n] - a - 2.f * t1s[n]) * (1.f / 3.f);
        }
        float t3a = __shfl_sync(~0u, t3, 0);
        float t3b = __shfl_sync(~0u, t3, 16);
        float xa  = xs[2 * p],  xb  = xs[2 * p + 1];
        float ta1 = t1s[2 * p], tb1 = t1s[2 * p + 1];
        float ta2 = t2s[2 * p], tb2 = t2s[2 * p + 1];
        float oa = fmaf(xa, w0, fmaf(ta1, w1, fmaf(ta2, w2, fmaf(t3a, w3, bb))));
        float ob = fmaf(xb, w0, fmaf(tb1, w1, fmaf(tb2, w2, fmaf(t3b, w3, bb))));
        lsum += oa + ob;
        lsq  += oa * oa + ob * ob;
        g_out32[((size_t)(g * E2C + p)) * 32 + lane] = fmaxf(oa, ob);
    }
    atomicAdd(&s_sum[lane], lsum);
    atomicAdd(&s_sq[lane], lsq);
    __syncthreads();
    if (tid < 32) {
        atomicAdd(&g_acc0[tid],      (double)s_sum[tid]);
        atomicAdd(&g_acc0[32 + tid], (double)s_sq[tid]);
    }
}

// ---------------- act0: BN0 finalize (in-block) + BN0 + LeakyReLU (float4) ----
__global__ void kAct0v(const float* __restrict__ g0, const float* __restrict__ be0) {
    __shared__ float s_sc[32], s_sh[32];
    int tid = threadIdx.x;
    if (tid < 32) {
        double mean = g_acc0[tid] * INV_N1;
        double var  = g_acc0[32 + tid] * INV_N1 - mean * mean;
        float scl = g0[tid] * rsqrtf((float)var + EPSBN);
        s_sc[tid] = scl;
        s_sh[tid] = be0[tid] - (float)mean * scl;
    }
    __syncthreads();
    int i = blockIdx.x * 256 + tid;                // over N2*8 float4s
    int cq = i & 7;
    float4 v = *(const float4*)&g_out32[i * 4];
    float4 sc = *(const float4*)&s_sc[cq * 4];
    float4 sh = *(const float4*)&s_sh[cq * 4];
    v.x = fmaf(v.x, sc.x, sh.x); v.x = v.x > 0.f ? v.x : SLOPE * v.x;
    v.y = fmaf(v.y, sc.y, sh.y); v.y = v.y > 0.f ? v.y : SLOPE * v.y;
    v.z = fmaf(v.z, sc.z, sh.z); v.z = v.z > 0.f ? v.z : SLOPE * v.z;
    v.w = fmaf(v.w, sc.w, sh.w); v.w = v.w > 0.f ? v.w : SLOPE * v.w;
    *(float4*)&g_xp[i * 4] = v;
}

// ---------------- pooled-graph 32-ch matvec, float4 form (round-14 proven) ----
// warp = 4 nodes; lane = (node_sub, channel-quad).
__global__ void kMV4(const float* __restrict__ vin, const float* __restrict__ p1,
                     const int* __restrict__ src, const float* __restrict__ ew,
                     float* __restrict__ out, float ca, float cb, float cc) {
    int warp = (blockIdx.x * blockDim.x + threadIdx.x) >> 5;   // node group of 4
    int lane = threadIdx.x & 31;
    int ns = lane >> 3, cq = lane & 7;
    int node = warp * 4 + ns;
    int e0 = node * 16 + cq;
    int   s0 = src[e0];     float w0 = ew[e0];
    int   s1 = src[e0 + 8]; float w1 = ew[e0 + 8];
    int sl = ns * 8;
    float4 acc = make_float4(0.f, 0.f, 0.f, 0.f);
#pragma unroll
    for (int j = 0; j < 8; j++) {
        int   sj = __shfl_sync(~0u, s0, sl + j);
        float wj = __shfl_sync(~0u, w0, sl + j);
        float4 v = *(const float4*)&vin[sj * 32 + cq * 4];
        acc.x = fmaf(wj, v.x, acc.x);
        acc.y = fmaf(wj, v.y, acc.y);
        acc.z = fmaf(wj, v.z, acc.z);
        acc.w = fmaf(wj, v.w, acc.w);
    }
#pragma unroll
    for (int j = 0; j < 8; j++) {
        int   sj = __shfl_sync(~0u, s1, sl + j);
        float wj = __shfl_sync(~0u, w1, sl + j);
        float4 v = *(const float4*)&vin[sj * 32 + cq * 4];
        acc.x = fmaf(wj, v.x, acc.x);
        acc.y = fmaf(wj, v.y, acc.y);
        acc.z = fmaf(wj, v.z, acc.z);
        acc.w = fmaf(wj, v.w, acc.w);
    }
    float4 own = *(const float4*)&vin[node * 32 + cq * 4];
    float4 o;
    o.x = ca * own.x + cc * acc.x;
    o.y = ca * own.y + cc * acc.y;
    o.z = ca * own.z + cc * acc.z;
    o.w = ca * own.w + cc * acc.w;
    if (cb != 0.f) {
        float4 p = *(const float4*)&p1[node * 32 + cq * 4];
        o.x += cb * p.x; o.y += cb * p.y; o.z += cb * p.z; o.w += cb * p.w;
    }
    *(float4*)&out[node * 32 + cq * 4] = o;
}

// ---------------- layer1 output GEMM + BN1 stats (round-14 proven) ------------
__global__ void kGemmOut1(const float* __restrict__ W1, const float* __restrict__ b1) {
    __shared__ float Wsh[128 * 32];
    __shared__ float Tsh[64 * 32];
    __shared__ float ssum[32], ssq[32];
    int tid = threadIdx.x, c = tid & 31, rg = tid >> 5;
    for (int i = tid; i < 4096; i += 256) Wsh[i] = W1[i];
    if (tid < 32) { ssum[tid] = 0.f; ssq[tid] = 0.f; }
    int n0 = blockIdx.x * 64;
    float acc[8];
#pragma unroll
    for (int q = 0; q < 8; q++) acc[q] = 0.f;
    const float* Tarr[4] = { g_xp, g_Ta, g_Tb, g_Tcc };
    for (int k = 0; k < 4; k++) {
        __syncthreads();
        const float* T = Tarr[k];
#pragma unroll
        for (int q = 0; q < 8; q++)
            Tsh[(rg + 8 * q) * 32 + c] = T[(n0 + rg + 8 * q) * 32 + c];
        __syncthreads();
#pragma unroll
        for (int i = 0; i < 32; i += 4) {
            float wa = Wsh[(k * 32 + i) * 32 + c];
            float wb = Wsh[(k * 32 + i + 1) * 32 + c];
            float wc = Wsh[(k * 32 + i + 2) * 32 + c];
            float wd = Wsh[(k * 32 + i + 3) * 32 + c];
#pragma unroll
            for (int q = 0; q < 8; q++) {
                float4 t = *(const float4*)&Tsh[(rg + 8 * q) * 32 + i];
                acc[q] += t.x * wa + t.y * wb + t.z * wc + t.w * wd;
            }
        }
    }
    float bv = b1[c];
    float lsum = 0.f, lsq = 0.f;
#pragma unroll
    for (int q = 0; q < 8; q++) {
        float o = acc[q] + bv;
        g_out32[(n0 + rg + 8 * q) * 32 + c] = o;
        lsum += o; lsq += o * o;
    }
    atomicAdd(&ssum[c], lsum);
    atomicAdd(&ssq[c], lsq);
    __syncthreads();
    if (tid < 32) {
        atomicAdd(&g_acc1[tid], (double)ssum[tid]);
        atomicAdd(&g_acc1[32 + tid], (double)ssq[tid]);
    }
}

// ---------------- layer2 input: BN1 finalize + act + project to 4 channels ----
__global__ void kAct1Y(const float* __restrict__ W2,
                       const float* __restrict__ g1, const float* __restrict__ be1) {
    __shared__ float s_sc[32], s_sh[32];
    int tid = threadIdx.x;
    if (tid < 32) {
        double mean = g_acc1[tid] * INV_N2;
        double var  = g_acc1[32 + tid] * INV_N2 - mean * mean;
        float scl = g1[tid] * rsqrtf((float)var + EPSBN);
        s_sc[tid] = scl;
        s_sh[tid] = be1[tid] - (float)mean * scl;
    }
    __syncthreads();
    int warp = (blockIdx.x * blockDim.x + tid) >> 5;   // = node
    int lane = tid & 31;
    float o = g_out32[warp * 32 + lane];
    float v = o * s_sc[lane] + s_sh[lane];
    v = v > 0.f ? v : SLOPE * v;
    float y0, y1, y2, y3;
    {
        float p = v * W2[lane];
#pragma unroll
        for (int off = 16; off; off >>= 1) p += __shfl_xor_sync(~0u, p, off);
        y0 = p;
    }
    {
        float p = v * W2[32 + lane];
#pragma unroll
        for (int off = 16; off; off >>= 1) p += __shfl_xor_sync(~0u, p, off);
        y1 = p;
    }
    {
        float p = v * W2[64 + lane];
#pragma unroll
        for (int off = 16; off; off >>= 1) p += __shfl_xor_sync(~0u, p, off);
        y2 = p;
    }
    {
        float p = v * W2[96 + lane];
#pragma unroll
        for (int off = 16; off; off >>= 1) p += __shfl_xor_sync(~0u, p, off);
        y3 = p;
    }
    if (lane < 4) {
        float val = (lane == 0) ? y0 : (lane == 1) ? y1 : (lane == 2) ? y2 : y3;
        g_Y[warp * 4 + lane] = val;
    }
}

// ---------------- 4-channel matvec on Y-field (layer2 recurrence) -------------
__global__ void kMVY(const float* __restrict__ vin, const float* __restrict__ p1,
                     const int* __restrict__ src, const float* __restrict__ ew,
                     float* __restrict__ out, float ca, float cb, float cc) {
    __shared__ int   s_src[16 * 65];
    __shared__ float s_ew [16 * 65];
    int tid = threadIdx.x;
    int e0 = blockIdx.x * 1024;
#pragma unroll
    for (int t = tid; t < 1024; t += 256) {
        int j = t & 15, local = t >> 4;
        s_src[j * 65 + local] = src[e0 + t];
        s_ew [j * 65 + local] = ew [e0 + t];
    }
    __syncthreads();
    int lane = tid & 31;
    int local = (tid >> 5) * 8 + (lane >> 2);   // node within block
    int ch = lane & 3;
    int node = blockIdx.x * 64 + local;
    float acc = 0.f;
#pragma unroll
    for (int j = 0; j < 16; j++) {
        int s   = s_src[j * 65 + local];
        float w = s_ew [j * 65 + local];
        acc += w * vin[s * 4 + ch];
    }
    float o = ca * vin[node * 4 + ch] + cc * acc;
    if (cb != 0.f) o += cb * p1[node * 4 + ch];
    out[node * 4 + ch] = o;
}

// final layer2 step: u3 = (5 U2 - L U2 - 2 U1)/3 ; z = Y0 + U1_1 + U2_2 + u3_3 + b2
__global__ void kMVY3C(const int* __restrict__ src, const float* __restrict__ ew,
                       const float* __restrict__ b2) {
    __shared__ int   s_src[16 * 65];
    __shared__ float s_ew [16 * 65];
    __shared__ float bs[2];
    int tid = threadIdx.x;
    int e0 = blockIdx.x * 1024;
    if (tid < 2) bs[tid] = 0.f;
#pragma unroll
    for (int t = tid; t < 1024; t += 256) {
        int j = t & 15, local = t >> 4;
        s_src[j * 65 + local] = src[e0 + t];
        s_ew [j * 65 + local] = ew [e0 + t];
    }
    __syncthreads();
    int lane = tid & 31;
    int local = (tid >> 5) * 8 + (lane >> 2);
    int ch = lane & 3;
    int node = blockIdx.x * 64 + local;
    float acc = 0.f;
#pragma unroll
    for (int j = 0; j < 16; j++) {
        int s   = s_src[j * 65 + local];
        float w = s_ew [j * 65 + local];
        acc += w * g_U2[s * 4 + ch];
    }
    float u2v = g_U2[node * 4 + ch];
    float u1v = g_U1[node * 4 + ch];
    float yv  = g_Y [node * 4 + ch];
    float u3  = (5.f * u2v - acc - 2.f * u1v) * (1.f / 3.f);
    int base = lane & ~3;
    float zY  = __shfl_sync(~0u, yv,  base + 0);
    float zU1 = __shfl_sync(~0u, u1v, base + 1);
    float zU2 = __shfl_sync(~0u, u2v, base + 2);
    float zU3 = __shfl_sync(~0u, u3,  base + 3);
    if (ch == 0) {
        float z = zY + zU1 + zU2 + zU3 + b2[0];
        g_z[node] = z;
        atomicAdd(&bs[0], z);
        atomicAdd(&bs[1], z * z);
    }
    __syncthreads();
    if (tid == 0) {
        atomicAdd(&g_acc2[0], (double)bs[0]);
        atomicAdd(&g_acc2[1], (double)bs[1]);
    }
}

// ---------------- MLP head ----------------
// D1 folds BN2 finalize (from g_acc2) + leaky + lin1
__global__ void kD1(const float* __restrict__ lin1W, const float* __restrict__ lin1b,
                    const float* __restrict__ g2, const float* __restrict__ be2) {
    __shared__ float As[16][64];
    __shared__ float Ws[64][8];
    int tid = threadIdx.x;
    int c = tid & 7, r = tid >> 3;
    int c0 = (blockIdx.x & 31) * 8;
    int r0 = (blockIdx.x >> 5) * 16;
    float scale, shift;
    {
        double mean = g_acc2[0] * INV_N2;
        double var  = g_acc2[1] * INV_N2 - mean * mean;
        scale = g2[0] * rsqrtf((float)var + EPSBN);
        shift = be2[0] - (float)mean * scale;
    }
    float acc = 0.f;
    for (int e0 = 0; e0 < E2C; e0 += 64) {
        __syncthreads();
        for (int t = tid; t < 1024; t += 128) {
            int rr = t >> 6, ii = t & 63, e = e0 + ii;
            float v = 0.f;
            if (e < E2C) {
                float z = g_z[(r0 + rr) * E2C + e] * scale + shift;
                v = z > 0.f ? z : SLOPE * z;
            }
            As[rr][ii] = v;
        }
        for (int t = tid; t < 512; t += 128) {
            int ii = t >> 3, cc = t & 7, e = e0 + ii;
            Ws[ii][cc] = (e < E2C) ? lin1W[e * 256 + c0 + cc] : 0.f;
        }
        __syncthreads();
#pragma unroll 8
        for (int i = 0; i < 64; i++) acc += As[r][i] * Ws[i][c];
    }
    g_H1[(r0 + r) * 256 + c0 + c] = acc + lin1b[c0 + c];
}

__global__ void kD2(const float* __restrict__ bn1g, const float* __restrict__ bn1b,
                    const float* __restrict__ lin2W, const float* __restrict__ lin2b) {
    __shared__ float sc[256], sh[256], As[2][256];
    int tid = threadIdx.x;
    {
        int col = tid;
        float s = 0.f, q = 0.f;
        for (int r = 0; r < 64; r++) { float v = g_H1[r * 256 + col]; s += v; q += v * v; }
        float mean = s * (1.f / 64.f);
        float var  = q * (1.f / 64.f) - mean * mean;
        float scl = bn1g[col] * rsqrtf(var + EPSBN);
        sc[col] = scl; sh[col] = bn1b[col] - mean * scl;
    }
    __syncthreads();
    int r0 = blockIdx.x * 2;
    for (int t = tid; t < 512; t += 256) {
        int rr = t >> 8, k = t & 255;
        float v = g_H1[(r0 + rr) * 256 + k] * sc[k] + sh[k];
        As[rr][k] = v > 0.f ? v : 0.f;
    }
    __syncthreads();
    int c = tid & 127, rr = tid >> 7;
    float acc = lin2b[c];
#pragma unroll 8
    for (int k = 0; k < 256; k++) acc += As[rr][k] * lin2W[k * 128 + c];
    g_H2[(r0 + rr) * 128 + c] = acc;
}

__global__ void kD3(const float* __restrict__ bn2g, const float* __restrict__ bn2b,
                    const float* __restrict__ lin3W, const float* __restrict__ lin3b,
                    float* __restrict__ out) {
    __shared__ float sc[128], sh[128];
    int tid = threadIdx.x;
    if (tid < 128) {
        float s = 0.f, q = 0.f;
        for (int r = 0; r < 64; r++) { float v = g_H2[r * 128 + tid]; s += v; q += v * v; }
        float mean = s * (1.f / 64.f);
        float var  = q * (1.f / 64.f) - mean * mean;
        float scl = bn2g[tid] * rsqrtf(var + EPSBN);
        sc[tid] = scl; sh[tid] = bn2b[tid] - mean * scl;
    }
    __syncthreads();
    int lane = tid & 31, w = tid >> 5;
    for (int r = w; r < 64; r += 8) {
        float acc = 0.f;
        for (int kk = lane; kk < 128; kk += 32) {
            float v = g_H2[r * 128 + kk] * sc[kk] + sh[kk];
            v = v > 0.f ? v : 0.f;
            acc += v * lin3W[kk];
        }
#pragma unroll
        for (int off = 16; off; off >>= 1)
            acc += __shfl_xor_sync(0xffffffffu, acc, off);
        if (lane == 0) out[r] = acc + lin3b[0];
    }
}

// ---------------- host launcher ----------------
extern "C" void kernel_launch(void* const* d_in, const int* in_sizes, int n_in,
                              void* d_out, int out_size) {
    const float* x    = (const float*)d_in[0];
    const int*   src1 = (const int*)  d_in[1];
    const float* ew1  = (const float*)d_in[2];
    const int*   src2 = (const int*)  d_in[3];
    const float* ew2  = (const float*)d_in[4];
    const float* W0 = (const float*)d_in[5];
    const float* b0 = (const float*)d_in[6];
    const float* g0 = (const float*)d_in[7];
    const float* be0= (const float*)d_in[8];
    const float* W1 = (const float*)d_in[9];
    const float* b1 = (const float*)d_in[10];
    const float* g1 = (const float*)d_in[11];
    const float* be1= (const float*)d_in[12];
    const float* W2 = (const float*)d_in[13];
    const float* b2 = (const float*)d_in[14];
    const float* g2 = (const float*)d_in[15];
    const float* be2= (const float*)d_in[16];
    const float* lin1W = (const float*)d_in[17];
    const float* lin1b = (const float*)d_in[18];
    const float* bn1g  = (const float*)d_in[19];
    const float* bn1b  = (const float*)d_in[20];
    const float* lin2W = (const float*)d_in[21];
    const float* lin2b = (const float*)d_in[22];
    const float* bn2g  = (const float*)d_in[23];
    const float* bn2b  = (const float*)d_in[24];
    const float* lin3W = (const float*)d_in[25];
    const float* lin3b = (const float*)d_in[26];
    float* out = (float*)d_out;

    float *pXp, *pTa, *pTb, *pTcc, *pY, *pU1, *pU2;
    cudaGetSymbolAddress((void**)&pXp,  g_xp);
    cudaGetSymbolAddress((void**)&pTa,  g_Ta);
    cudaGetSymbolAddress((void**)&pTb,  g_Tb);
    cudaGetSymbolAddress((void**)&pTcc, g_Tcc);
    cudaGetSymbolAddress((void**)&pY,   g_Y);
    cudaGetSymbolAddress((void**)&pU1,  g_U1);
    cudaGetSymbolAddress((void**)&pU2,  g_U2);

    const int kL0smem = 3 * EE * (int)sizeof(float);   // 107,736 B
    cudaFuncSetAttribute(kL0, cudaFuncAttributeMaxDynamicSharedMemorySize, kL0smem);

    kZero<<<1, 256>>>();

    // ---- layer0 fused ----
    kL0<<<BB, 1024, kL0smem>>>(x, src1, ew1, W0, b0);
    kAct0v<<<(N2 * 8) / 256, 256>>>(g0, be0);   // BN0 finalize folded in

    // ---- layer1 (32 channels, pooled graph) — round-14 float4 gather matvecs ----
    kMV4<<<N2 / 32, 256>>>(pXp, pXp, src2, ew2, pTa, 1.0f, 0.0f, -1.0f);
    kMV4<<<N2 / 32, 256>>>(pTa, pXp, src2, ew2, pTb, 1.5f, -0.5f, -0.5f);
    kMV4<<<N2 / 32, 256>>>(pTb, pTa, src2, ew2, pTcc, 5.f/3.f, -2.f/3.f, -1.f/3.f);
    kGemmOut1<<<N2 / 64, 256>>>(W1, b1);

    // ---- layer2 collapsed to 4-channel recurrence (BN1 folded into kAct1Y) ----
    kAct1Y<<<N2 / 8, 256>>>(W2, g1, be1);
    kMVY<<<N2 / 64, 256>>>(pY,  pY, src2, ew2, pU1, 1.0f, 0.0f, -1.0f);
    kMVY<<<N2 / 64, 256>>>(pU1, pY, src2, ew2, pU2, 1.5f, -0.5f, -0.5f);
    kMVY3C<<<N2 / 64, 256>>>(src2, ew2, b2);

    // ---- MLP head (BN2 finalize folded into kD1) ----
    kD1<<<128, 128>>>(lin1W, lin1b, g2, be2);
    kD2<<<32, 256>>>(bn1g, bn1b, lin2W, lin2b);
    kD3<<<1, 256>>>(bn2g, bn2b, lin3W, lin3b, out);
}